// round 11
// baseline (speedup 1.0000x reference)
#include <cuda_runtime.h>
#include <cstdint>

// GraphAttention: V=500000, D=128, B=4096, T=3, K=64  (rows = 12288)
// Best-known compute body (R2/R9: warp/row, compaction, pad-8, streaming
// hints; ~4.7TB/s gather ceiling) + persistent single-wave grid with
// warp-level work stealing. Counter never resets: each launch performs a
// deterministic EPOCH = NUM_ROWS + TOTAL_WARPS increments (every warp exits
// on exactly one failed grab), so row = ctr % EPOCH is replay-safe with no
// reset/fence epilogue.

#define NUM_ROWS  (4096 * 3)
#define KNEIGH    64
#define DDIM      128
#define INV_ATT_SCALE (1.0f / 15.0f)
#define LN_EPS    1e-5f
#define WPB       8
#define THREADS   (WPB * 32)
#define CHUNK     8
#define NBLOCKS   1036                       // ~one full wave at 7 blocks/SM
#define TOTAL_WARPS (NBLOCKS * WPB)          // 8288
#define EPOCH     ((unsigned)(NUM_ROWS + TOTAL_WARPS))   // 20576 grabs/launch

__device__ unsigned int g_row_ctr = 0;       // monotonically increasing

__device__ __forceinline__ float warp_sum(float v) {
    v += __shfl_xor_sync(0xffffffffu, v, 16);
    v += __shfl_xor_sync(0xffffffffu, v, 8);
    v += __shfl_xor_sync(0xffffffffu, v, 4);
    v += __shfl_xor_sync(0xffffffffu, v, 2);
    v += __shfl_xor_sync(0xffffffffu, v, 1);
    return v;
}

__global__ __launch_bounds__(THREADS)
void graph_attention_kernel(const int*   __restrict__ node_ids,      // [B,3]
                            const int*   __restrict__ neighbor_ids,  // [B,3,K]
                            const int*   __restrict__ neighbor_mask, // [B,3,K]
                            const float* __restrict__ emb,           // [V,D]
                            const float* __restrict__ gamma,         // [D]
                            const float* __restrict__ beta,          // [D]
                            float*       __restrict__ out)           // [B,3,D]
{
    __shared__ int s_act[WPB][KNEIGH];

    const int w    = threadIdx.x >> 5;
    const int lane = threadIdx.x & 31;
    const unsigned full = 0xffffffffu;

    const float4* __restrict__ embv = reinterpret_cast<const float4*>(emb);

    for (;;) {
        // ---- steal one row (lane 0 grabs, broadcast) ----
        unsigned v = 0;
        if (lane == 0) v = atomicAdd(&g_row_ctr, 1u);
        v = __shfl_sync(full, v, 0);
        const unsigned pos = v % EPOCH;
        if (pos >= (unsigned)NUM_ROWS) break;   // exactly one failed grab per warp
        const int row = (int)pos;

        const int nid = __ldcs(&node_ids[row]);
        const float4 node = embv[(size_t)nid * 32 + lane];

        // ---- warp-level compaction of active neighbors ----
        const int* __restrict__ nids  = neighbor_ids  + (size_t)row * KNEIGH;
        const int* __restrict__ nmask = neighbor_mask + (size_t)row * KNEIGH;

        const int m0  = __ldcs(&nmask[lane]);
        const int m1  = __ldcs(&nmask[lane + 32]);
        const int id0 = __ldcs(&nids[lane]);
        const int id1 = __ldcs(&nids[lane + 32]);

        const unsigned b0 = __ballot_sync(full, m0 != 0);
        const unsigned b1 = __ballot_sync(full, m1 != 0);
        const int c0  = __popc(b0);
        const int cnt = c0 + __popc(b1);
        const unsigned lt = (1u << lane) - 1u;

        if (m0) s_act[w][__popc(b0 & lt)]      = id0;
        if (m1) s_act[w][c0 + __popc(b1 & lt)] = id1;

        // pad to a multiple of 8 with dummy id 0 (weight-masked to zero)
        const int pad8 = (cnt + 7) & ~7;
        if (lane < pad8 - cnt) s_act[w][cnt + lane] = 0;
        __syncwarp(full);

        const int* __restrict__ list = s_act[w];
        const int np = pad8 >> 3;

        float4 acc = make_float4(0.f, 0.f, 0.f, 0.f);

        for (int c = 0; c < np; ++c) {
            const int base = c * CHUNK;

            float4 n4[CHUNK];
            #pragma unroll
            for (int j = 0; j < CHUNK; ++j) {
                const int nb = list[base + j];
                n4[j] = embv[(size_t)nb * 32 + lane];
            }

            float p[CHUNK];
            #pragma unroll
            for (int j = 0; j < CHUNK; ++j)
                p[j] = n4[j].x * node.x + n4[j].y * node.y
                     + n4[j].z * node.z + n4[j].w * node.w;

            #pragma unroll
            for (int j = 0; j < CHUNK; ++j)
                p[j] = warp_sum(p[j]);

            #pragma unroll
            for (int j = 0; j < CHUNK; ++j) {
                const float att = (base + j < cnt) ? p[j] * INV_ATT_SCALE : 0.0f;
                acc.x += att * n4[j].x;
                acc.y += att * n4[j].y;
                acc.z += att * n4[j].z;
                acc.w += att * n4[j].w;
            }
        }

        // ---- x = node + att_out, LayerNorm over D=128 ----
        float4 x;
        x.x = node.x + acc.x;
        x.y = node.y + acc.y;
        x.z = node.z + acc.z;
        x.w = node.w + acc.w;

        const float mu = warp_sum(x.x + x.y + x.z + x.w) * (1.0f / DDIM);

        const float dx0 = x.x - mu, dx1 = x.y - mu, dx2 = x.z - mu, dx3 = x.w - mu;
        const float var = warp_sum(dx0*dx0 + dx1*dx1 + dx2*dx2 + dx3*dx3) * (1.0f / DDIM);
        const float r = rsqrtf(var + LN_EPS);

        const float4 g = reinterpret_cast<const float4*>(gamma)[lane];
        const float4 b = reinterpret_cast<const float4*>(beta)[lane];

        float4 o;
        o.x = dx0 * r * g.x + b.x;
        o.y = dx1 * r * g.y + b.y;
        o.z = dx2 * r * g.z + b.z;
        o.w = dx3 * r * g.w + b.w;

        __stcs(&reinterpret_cast<float4*>(out)[(size_t)row * 32 + lane], o);
    }
}

extern "C" void kernel_launch(void* const* d_in, const int* in_sizes, int n_in,
                              void* d_out, int out_size)
{
    const int*   node_ids      = (const int*)  d_in[0];
    const int*   neighbor_ids  = (const int*)  d_in[1];
    const int*   neighbor_mask = (const int*)  d_in[2];
    const float* emb           = (const float*)d_in[3];
    const float* gamma         = (const float*)d_in[4];
    const float* beta          = (const float*)d_in[5];
    float*       out           = (float*)d_out;

    graph_attention_kernel<<<NBLOCKS, THREADS>>>(node_ids, neighbor_ids, neighbor_mask,
                                                 emb, gamma, beta, out);
}

// round 12
// speedup vs baseline: 1.0045x; 1.0045x over previous
#include <cuda_runtime.h>
#include <cstdint>

// GraphAttention: V=500000, D=128, B=4096, T=3, K=64  (rows = 12288)
// Best-known compute body (R2/R9: warp/row, compaction, pad-8, streaming
// hints; ~4.7TB/s gather ceiling) + persistent single-wave grid with
// warp-level work stealing. Counter never resets: each launch performs a
// deterministic EPOCH = NUM_ROWS + TOTAL_WARPS increments (every warp exits
// on exactly one failed grab), so row = ctr % EPOCH is replay-safe with no
// reset/fence epilogue.

#define NUM_ROWS  (4096 * 3)
#define KNEIGH    64
#define DDIM      128
#define INV_ATT_SCALE (1.0f / 15.0f)
#define LN_EPS    1e-5f
#define WPB       8
#define THREADS   (WPB * 32)
#define CHUNK     8
#define NBLOCKS   1036                       // ~one full wave at 7 blocks/SM
#define TOTAL_WARPS (NBLOCKS * WPB)          // 8288
#define EPOCH     ((unsigned)(NUM_ROWS + TOTAL_WARPS))   // 20576 grabs/launch

__device__ unsigned int g_row_ctr = 0;       // monotonically increasing

__device__ __forceinline__ float warp_sum(float v) {
    v += __shfl_xor_sync(0xffffffffu, v, 16);
    v += __shfl_xor_sync(0xffffffffu, v, 8);
    v += __shfl_xor_sync(0xffffffffu, v, 4);
    v += __shfl_xor_sync(0xffffffffu, v, 2);
    v += __shfl_xor_sync(0xffffffffu, v, 1);
    return v;
}

__global__ __launch_bounds__(THREADS)
void graph_attention_kernel(const int*   __restrict__ node_ids,      // [B,3]
                            const int*   __restrict__ neighbor_ids,  // [B,3,K]
                            const int*   __restrict__ neighbor_mask, // [B,3,K]
                            const float* __restrict__ emb,           // [V,D]
                            const float* __restrict__ gamma,         // [D]
                            const float* __restrict__ beta,          // [D]
                            float*       __restrict__ out)           // [B,3,D]
{
    __shared__ int s_act[WPB][KNEIGH];

    const int w    = threadIdx.x >> 5;
    const int lane = threadIdx.x & 31;
    const unsigned full = 0xffffffffu;

    const float4* __restrict__ embv = reinterpret_cast<const float4*>(emb);

    for (;;) {
        // ---- steal one row (lane 0 grabs, broadcast) ----
        unsigned v = 0;
        if (lane == 0) v = atomicAdd(&g_row_ctr, 1u);
        v = __shfl_sync(full, v, 0);
        const unsigned pos = v % EPOCH;
        if (pos >= (unsigned)NUM_ROWS) break;   // exactly one failed grab per warp
        const int row = (int)pos;

        const int nid = __ldcs(&node_ids[row]);
        const float4 node = embv[(size_t)nid * 32 + lane];

        // ---- warp-level compaction of active neighbors ----
        const int* __restrict__ nids  = neighbor_ids  + (size_t)row * KNEIGH;
        const int* __restrict__ nmask = neighbor_mask + (size_t)row * KNEIGH;

        const int m0  = __ldcs(&nmask[lane]);
        const int m1  = __ldcs(&nmask[lane + 32]);
        const int id0 = __ldcs(&nids[lane]);
        const int id1 = __ldcs(&nids[lane + 32]);

        const unsigned b0 = __ballot_sync(full, m0 != 0);
        const unsigned b1 = __ballot_sync(full, m1 != 0);
        const int c0  = __popc(b0);
        const int cnt = c0 + __popc(b1);
        const unsigned lt = (1u << lane) - 1u;

        if (m0) s_act[w][__popc(b0 & lt)]      = id0;
        if (m1) s_act[w][c0 + __popc(b1 & lt)] = id1;

        // pad to a multiple of 8 with dummy id 0 (weight-masked to zero)
        const int pad8 = (cnt + 7) & ~7;
        if (lane < pad8 - cnt) s_act[w][cnt + lane] = 0;
        __syncwarp(full);

        const int* __restrict__ list = s_act[w];
        const int np = pad8 >> 3;

        float4 acc = make_float4(0.f, 0.f, 0.f, 0.f);

        for (int c = 0; c < np; ++c) {
            const int base = c * CHUNK;

            float4 n4[CHUNK];
            #pragma unroll
            for (int j = 0; j < CHUNK; ++j) {
                const int nb = list[base + j];
                n4[j] = embv[(size_t)nb * 32 + lane];
            }

            float p[CHUNK];
            #pragma unroll
            for (int j = 0; j < CHUNK; ++j)
                p[j] = n4[j].x * node.x + n4[j].y * node.y
                     + n4[j].z * node.z + n4[j].w * node.w;

            #pragma unroll
            for (int j = 0; j < CHUNK; ++j)
                p[j] = warp_sum(p[j]);

            #pragma unroll
            for (int j = 0; j < CHUNK; ++j) {
                const float att = (base + j < cnt) ? p[j] * INV_ATT_SCALE : 0.0f;
                acc.x += att * n4[j].x;
                acc.y += att * n4[j].y;
                acc.z += att * n4[j].z;
                acc.w += att * n4[j].w;
            }
        }

        // ---- x = node + att_out, LayerNorm over D=128 ----
        float4 x;
        x.x = node.x + acc.x;
        x.y = node.y + acc.y;
        x.z = node.z + acc.z;
        x.w = node.w + acc.w;

        const float mu = warp_sum(x.x + x.y + x.z + x.w) * (1.0f / DDIM);

        const float dx0 = x.x - mu, dx1 = x.y - mu, dx2 = x.z - mu, dx3 = x.w - mu;
        const float var = warp_sum(dx0*dx0 + dx1*dx1 + dx2*dx2 + dx3*dx3) * (1.0f / DDIM);
        const float r = rsqrtf(var + LN_EPS);

        const float4 g = reinterpret_cast<const float4*>(gamma)[lane];
        const float4 b = reinterpret_cast<const float4*>(beta)[lane];

        float4 o;
        o.x = dx0 * r * g.x + b.x;
        o.y = dx1 * r * g.y + b.y;
        o.z = dx2 * r * g.z + b.z;
        o.w = dx3 * r * g.w + b.w;

        __stcs(&reinterpret_cast<float4*>(out)[(size_t)row * 32 + lane], o);
    }
}

extern "C" void kernel_launch(void* const* d_in, const int* in_sizes, int n_in,
                              void* d_out, int out_size)
{
    const int*   node_ids      = (const int*)  d_in[0];
    const int*   neighbor_ids  = (const int*)  d_in[1];
    const int*   neighbor_mask = (const int*)  d_in[2];
    const float* emb           = (const float*)d_in[3];
    const float* gamma         = (const float*)d_in[4];
    const float* beta          = (const float*)d_in[5];
    float*       out           = (float*)d_out;

    graph_attention_kernel<<<NBLOCKS, THREADS>>>(node_ids, neighbor_ids, neighbor_mask,
                                                 emb, gamma, beta, out);
}

// round 14
// speedup vs baseline: 1.1719x; 1.1667x over previous
#include <cuda_runtime.h>
#include <cstdint>

// GraphAttention: V=500000, D=128, B=4096, T=3, K=64  (rows = 12288)
// Trunk = R2/R9 proven body (warp/row, warp compaction, pad-8, streaming
// hints on one-shot data; ~4.7TB/s random-gather ceiling). Single-variable
// experiment this round: WPB 8 -> 4 (128-thread blocks) to halve the block
// retirement quantum for the partial-wave tail; registers unchanged (~36).

#define NUM_ROWS  (4096 * 3)
#define KNEIGH    64
#define DDIM      128
#define INV_ATT_SCALE (1.0f / 15.0f)
#define LN_EPS    1e-5f
#define WPB       4
#define THREADS   (WPB * 32)
#define CHUNK     8

__device__ __forceinline__ float warp_sum(float v) {
    v += __shfl_xor_sync(0xffffffffu, v, 16);
    v += __shfl_xor_sync(0xffffffffu, v, 8);
    v += __shfl_xor_sync(0xffffffffu, v, 4);
    v += __shfl_xor_sync(0xffffffffu, v, 2);
    v += __shfl_xor_sync(0xffffffffu, v, 1);
    return v;
}

__global__ __launch_bounds__(THREADS)
void graph_attention_kernel(const int*   __restrict__ node_ids,      // [B,3]
                            const int*   __restrict__ neighbor_ids,  // [B,3,K]
                            const int*   __restrict__ neighbor_mask, // [B,3,K]
                            const float* __restrict__ emb,           // [V,D]
                            const float* __restrict__ gamma,         // [D]
                            const float* __restrict__ beta,          // [D]
                            float*       __restrict__ out)           // [B,3,D]
{
    __shared__ int s_act[WPB][KNEIGH];

    const int w    = threadIdx.x >> 5;
    const int lane = threadIdx.x & 31;
    const int row  = blockIdx.x * WPB + w;   // grid sized exactly

    const float4* __restrict__ embv = reinterpret_cast<const float4*>(emb);

    const int nid = __ldcs(&node_ids[row]);
    const float4 node = embv[(size_t)nid * 32 + lane];

    // ---- warp-level compaction of active neighbors ----
    const int* __restrict__ nids  = neighbor_ids  + (size_t)row * KNEIGH;
    const int* __restrict__ nmask = neighbor_mask + (size_t)row * KNEIGH;

    const int m0  = __ldcs(&nmask[lane]);
    const int m1  = __ldcs(&nmask[lane + 32]);
    const int id0 = __ldcs(&nids[lane]);
    const int id1 = __ldcs(&nids[lane + 32]);

    const unsigned full = 0xffffffffu;
    const unsigned b0 = __ballot_sync(full, m0 != 0);
    const unsigned b1 = __ballot_sync(full, m1 != 0);
    const int c0  = __popc(b0);
    const int cnt = c0 + __popc(b1);
    const unsigned lt = (1u << lane) - 1u;

    if (m0) s_act[w][__popc(b0 & lt)]      = id0;
    if (m1) s_act[w][c0 + __popc(b1 & lt)] = id1;

    // pad to a multiple of 8 with dummy id 0 (weight-masked to zero)
    const int pad8 = (cnt + 7) & ~7;         // <= 64
    if (lane < pad8 - cnt) s_act[w][cnt + lane] = 0;
    __syncwarp(full);

    const int* __restrict__ list = s_act[w];
    const int np = pad8 >> 3;                // 0..8

    // ---- dense inner loop: 8 batched gathers per chunk, no remainder ----
    float4 acc = make_float4(0.f, 0.f, 0.f, 0.f);

    for (int c = 0; c < np; ++c) {
        const int base = c * CHUNK;

        float4 n4[CHUNK];
        #pragma unroll
        for (int j = 0; j < CHUNK; ++j) {
            const int nb = list[base + j];
            n4[j] = embv[(size_t)nb * 32 + lane];
        }

        float p[CHUNK];
        #pragma unroll
        for (int j = 0; j < CHUNK; ++j)
            p[j] = n4[j].x * node.x + n4[j].y * node.y
                 + n4[j].z * node.z + n4[j].w * node.w;

        #pragma unroll
        for (int j = 0; j < CHUNK; ++j)
            p[j] = warp_sum(p[j]);   // independent butterfly chains interleave

        #pragma unroll
        for (int j = 0; j < CHUNK; ++j) {
            const float att = (base + j < cnt) ? p[j] * INV_ATT_SCALE : 0.0f;
            acc.x += att * n4[j].x;
            acc.y += att * n4[j].y;
            acc.z += att * n4[j].z;
            acc.w += att * n4[j].w;
        }
    }

    // ---- x = node + att_out, LayerNorm over D=128 ----
    float4 x;
    x.x = node.x + acc.x;
    x.y = node.y + acc.y;
    x.z = node.z + acc.z;
    x.w = node.w + acc.w;

    const float mu = warp_sum(x.x + x.y + x.z + x.w) * (1.0f / DDIM);

    const float dx0 = x.x - mu, dx1 = x.y - mu, dx2 = x.z - mu, dx3 = x.w - mu;
    const float var = warp_sum(dx0*dx0 + dx1*dx1 + dx2*dx2 + dx3*dx3) * (1.0f / DDIM);
    const float r = rsqrtf(var + LN_EPS);

    const float4 g = reinterpret_cast<const float4*>(gamma)[lane];
    const float4 b = reinterpret_cast<const float4*>(beta)[lane];

    float4 o;
    o.x = dx0 * r * g.x + b.x;
    o.y = dx1 * r * g.y + b.y;
    o.z = dx2 * r * g.z + b.z;
    o.w = dx3 * r * g.w + b.w;

    // streaming store: output is never re-read; don't pollute L2
    __stcs(&reinterpret_cast<float4*>(out)[(size_t)row * 32 + lane], o);
}

extern "C" void kernel_launch(void* const* d_in, const int* in_sizes, int n_in,
                              void* d_out, int out_size)
{
    const int*   node_ids      = (const int*)  d_in[0];
    const int*   neighbor_ids  = (const int*)  d_in[1];
    const int*   neighbor_mask = (const int*)  d_in[2];
    const float* emb           = (const float*)d_in[3];
    const float* gamma         = (const float*)d_in[4];
    const float* beta          = (const float*)d_in[5];
    float*       out           = (float*)d_out;

    const int blocks = NUM_ROWS / WPB;       // 3072, exact

    graph_attention_kernel<<<blocks, THREADS>>>(node_ids, neighbor_ids, neighbor_mask,
                                                emb, gamma, beta, out);
}